// round 17
// baseline (speedup 1.0000x reference)
#include <cuda_runtime.h>
#include <cstdint>

#define DEV_INLINE __device__ __forceinline__
typedef unsigned long long ull;

// ---------------- scratch (device globals; no allocations allowed) ----------
__device__ float g_c1[16 * 1024 * 256];            // after conv1 + frame grouping
__device__ float g_c2[16 * 1024 * 256];            // after conv2
__device__ float g_c3[16 * 4096 * 256];            // after tconv
__device__ float g_gx[(size_t)16 * 8 * 4096 * 96]; // gates_x, GRU-CTA-sliced layout
__device__ float g_w2t[512 * 256];                 // W2 transposed: [kk][o]
__device__ float g_wihT[256 * 768];                // W_ih transposed: [c][g]
// GRU h exchange: merged (epoch<<32 | value_bits) words, double-buffered
__device__ ull g_hv[2 * 16 * 256];                 // [bin][batch][channel]

// ---------------- packed f32x2 helpers --------------------------------------
DEV_INLINE ull dup2(float x) {
    ull r; asm("mov.b64 %0, {%1, %1};" : "=l"(r) : "f"(x)); return r;
}
DEV_INLINE void fma2(ull& d, ull a, ull b) {
    asm("fma.rn.f32x2 %0, %1, %2, %0;" : "+l"(d) : "l"(a), "l"(b));
}
DEV_INLINE void unpack2(ull v, float& x, float& y) {
    asm("mov.b64 {%0, %1}, %2;" : "=f"(x), "=f"(y) : "l"(v));
}

// ---------------- fast activations (MUFU ex2 + rcp; rel err ~1e-6) ----------
DEV_INLINE float fast_tanh(float x) {
    x = fminf(15.f, fmaxf(-15.f, x));
    float e = __expf(2.f * x);
    return __fdividef(e - 1.f, e + 1.f);
}
DEV_INLINE float fast_sig(float x) {
    x = fminf(30.f, fmaxf(-30.f, x));
    return __fdividef(1.f, 1.f + __expf(-x));
}

// ---------------- relaxed 8B atomics through L2 (no acquire/release) --------
DEV_INLINE ull ld_relaxed_gpu_b64(const ull* p) {
    ull v;
    asm volatile("ld.relaxed.gpu.global.b64 %0, [%1];" : "=l"(v) : "l"(p) : "memory");
    return v;
}
DEV_INLINE void st_relaxed_gpu_b64(ull* p, ull v) {
    asm volatile("st.relaxed.gpu.global.b64 [%0], %1;" :: "l"(p), "l"(v) : "memory");
}
// ---------------- cp.async helpers ------------------------------------------
DEV_INLINE uint32_t smem_u32(const void* p) {
    return (uint32_t)__cvta_generic_to_shared(p);
}
DEV_INLINE void cp_async16(uint32_t saddr, const void* gptr) {
    asm volatile("cp.async.cg.shared.global [%0], [%1], 16;"
                 :: "r"(saddr), "l"(gptr) : "memory");
}
#define CP_COMMIT() asm volatile("cp.async.commit_group;" ::: "memory")
#define CP_WAIT0()  asm volatile("cp.async.wait_group 0;" ::: "memory")

// ============================================================================
// Kernel A: conv1 (k=1 pointwise, 47->64) + tanh + frame grouping (B,1024,256)
// ============================================================================
__global__ __launch_bounds__(256) void conv1_kernel(
    const float* __restrict__ feat, const float* __restrict__ W1,
    const float* __restrict__ b1)
{
    __shared__ float sW[64 * 47];
    __shared__ float sb[64];
    __shared__ float sx[32 * 47];
    const int tid = threadIdx.x;
    const int b = blockIdx.y;
    const int f0 = blockIdx.x * 32;
    for (int i = tid; i < 64 * 47; i += 256) sW[i] = W1[i];
    if (tid < 64) sb[tid] = b1[tid];
    const float* fp = feat + ((size_t)b * 4096 + f0) * 47;
    for (int i = tid; i < 32 * 47; i += 256) sx[i] = fp[i];
    __syncthreads();
#pragma unroll
    for (int r = 0; r < 8; r++) {
        int idx = tid + 256 * r;
        int f = idx >> 6, h = idx & 63;
        float acc = sb[h];
#pragma unroll
        for (int i = 0; i < 47; i++) acc = fmaf(sx[f * 47 + i], sW[h * 47 + i], acc);
        int gf = f0 + f;
        g_c1[((size_t)b * 1024 + (gf >> 2)) * 256 + ((gf & 3) << 6) + h] = fast_tanh(acc);
    }
}

// ============================================================================
// Prep: both weight transposes in ONE kernel.
// ============================================================================
__global__ __launch_bounds__(768) void prep_kernel(
    const float* __restrict__ W2, const float* __restrict__ W_ih)
{
    int blk = blockIdx.x;
    int t = threadIdx.x;
    if (blk < 512) {
        if (t < 256)
            g_w2t[blk * 256 + t] = W2[t * 512 + ((blk & 255) << 1) + (blk >> 8)];
    } else {
        int c = blk - 512;                 // 0..255
        g_wihT[c * 768 + t] = W_ih[t * 256 + c];
    }
}

// ============================================================================
// Pipelined GEMM (128x128 tile, BK=16, double-buffered smem):
//  - B tile via cp.async.cg; A tile via register staging (LDG one tile early)
//  - ONE __syncthreads per tile.
// ============================================================================
template <int MODE>
__global__ __launch_bounds__(256) void gemm_kernel(
    const float* __restrict__ Bext, const float* __restrict__ bias)
{
    __shared__ float As[2][16][136];
    __shared__ float Bs[2][16][128];
    const int tid = threadIdx.x;
    const int tx = tid & 15, ty = tid >> 4;
    const int m0 = blockIdx.x * 128;
    const int n0 = blockIdx.y * 128;
    constexpr int K   = (MODE == 0) ? 512 : 256;
    constexpr int NT  = K / 16;
    constexpr int Nld = (MODE == 0) ? 256 : (MODE == 1 ? 1024 : 768);
    const float* Bm = (MODE == 0) ? g_w2t : (MODE == 1 ? Bext : g_wihT);
    const float* Amat = (MODE == 1) ? g_c2 : g_c3;

    ull acc[8][4];
#pragma unroll
    for (int i = 0; i < 8; i++)
#pragma unroll
        for (int j = 0; j < 4; j++) acc[i][j] = 0ULL;

    float4 av[2];
    auto loadA = [&](int k0) {
#pragma unroll
        for (int it = 0; it < 2; it++) {
            int idx = tid + it * 256;
            int row = idx >> 2;
            int kq = (idx & 3) << 2;
            int m = m0 + row;
            if (MODE == 0) {
                if (k0 < 256) {
                    if ((m & 1023) != 0)
                        av[it] = *(const float4*)&g_c1[((size_t)m - 1) * 256 + k0 + kq];
                    else
                        av[it] = make_float4(0.f, 0.f, 0.f, 0.f);
                } else {
                    av[it] = *(const float4*)&g_c1[(size_t)m * 256 + (k0 - 256) + kq];
                }
            } else {
                av[it] = *(const float4*)&Amat[(size_t)m * 256 + k0 + kq];
            }
        }
    };
    auto storeA = [&](int buf) {
#pragma unroll
        for (int it = 0; it < 2; it++) {
            int idx = tid + it * 256;
            int row = idx >> 2;
            int kq = (idx & 3) << 2;
            As[buf][kq + 0][row] = av[it].x;
            As[buf][kq + 1][row] = av[it].y;
            As[buf][kq + 2][row] = av[it].z;
            As[buf][kq + 3][row] = av[it].w;
        }
    };
    auto issueB = [&](int k0, int buf) {
#pragma unroll
        for (int it = 0; it < 2; it++) {
            int idx = tid + it * 256;
            int kr = idx >> 5;
            int nq = (idx & 31) << 2;
            cp_async16(smem_u32(&Bs[buf][kr][nq]),
                       &Bm[(size_t)(k0 + kr) * Nld + n0 + nq]);
        }
    };

    loadA(0);
    issueB(0, 0);
    CP_COMMIT();
    storeA(0);
    CP_WAIT0();
    __syncthreads();

    for (int kt = 0; kt < NT; kt++) {
        const int cur = kt & 1;
        const int nxt = cur ^ 1;
        if (kt + 1 < NT) {
            loadA((kt + 1) * 16);
            issueB((kt + 1) * 16, nxt);
            CP_COMMIT();
        }
#pragma unroll
        for (int kk = 0; kk < 16; kk++) {
            float4 a0 = *(const float4*)&As[cur][kk][ty * 8];
            float4 a1 = *(const float4*)&As[cur][kk][ty * 8 + 4];
            ulonglong2 bb0 = *(const ulonglong2*)&Bs[cur][kk][tx * 8];
            ulonglong2 bb1 = *(const ulonglong2*)&Bs[cur][kk][tx * 8 + 4];
            ull ad[8] = {dup2(a0.x), dup2(a0.y), dup2(a0.z), dup2(a0.w),
                         dup2(a1.x), dup2(a1.y), dup2(a1.z), dup2(a1.w)};
            ull bp[4] = {bb0.x, bb0.y, bb1.x, bb1.y};
#pragma unroll
            for (int mm = 0; mm < 8; mm++)
#pragma unroll
                for (int np = 0; np < 4; np++) fma2(acc[mm][np], ad[mm], bp[np]);
        }
        if (kt + 1 < NT) {
            storeA(nxt);
            CP_WAIT0();
            __syncthreads();
        }
    }
#pragma unroll
    for (int mm = 0; mm < 8; mm++) {
        int m = m0 + ty * 8 + mm;
#pragma unroll
        for (int np = 0; np < 4; np++) {
            float f0, f1;
            unpack2(acc[mm][np], f0, f1);
#pragma unroll
            for (int e = 0; e < 2; e++) {
                float f = e ? f1 : f0;
                int n = n0 + tx * 8 + np * 2 + e;
                if (MODE == 0) {
                    g_c2[(size_t)m * 256 + n] = fast_tanh(f + __ldg(&bias[n]));
                } else if (MODE == 1) {
                    int o = n >> 2, kcv = n & 3;
                    float v = fast_tanh(f + __ldg(&bias[o]));
                    int bb = m >> 10, t = m & 1023;
                    g_c3[((size_t)bb * 4096 + 4 * t + kcv) * 256 + o] = v;
                } else {
                    float v = f + __ldg(&bias[n]);
                    int bb = m >> 12, t = m & 4095;
                    int gate = n >> 8, ch = n & 255;
                    int sl = ch >> 5, loc = (gate << 5) + (ch & 31);
                    g_gx[((size_t)(bb * 8 + sl) * 4096 + t) * 96 + loc] = v;
                }
            }
        }
    }
}

// ============================================================================
// GRU: 64 CTAs (8 batch-pairs x 8 slots). TWO interleaved chains per CTA
// (batches pr and pr+8, SAME slot s -> identical W_hh rows, no extra weight
// regs). Per iteration t (advances both chains one step):
//   gemv_A -> bar -> [act_A + publish_A(t+1) || gather_B(t)] -> bar ->
//   gemv_B -> bar -> [act_B + publish_B(t+1) || gather_A(t+1)] -> bar
// Each chain's publish->gather window spans the other chain's gemv+2 bars,
// hiding the ~540-cyc L2 exchange chain. Exchange protocol = R12 (merged
// epoch|value relaxed words); replay-safe by exact-epoch + determinism.
// ============================================================================
__global__ void __launch_bounds__(384, 1)
gru_kernel(const float* __restrict__ W_hh, const float* __restrict__ b_hh,
           float* __restrict__ out)
{
    __shared__ __align__(16) float h_buf[2][2][272]; // [chain][bin][swizzled]
    __shared__ float gates_s[2][96];
    const int tid = threadIdx.x;
    const int s = blockIdx.x & 7;
    const int pr = blockIdx.x >> 3;        // pair 0..7
    const int bA = pr, bB = pr + 8;
    const int p = tid >> 2, kc = tid & 3;  // 96 rows x 4 K-chunks of 64
    const int grow = ((p >> 5) << 8) + (s << 5) + (p & 31);
    const int warp = tid >> 5, lane = tid & 31;

    // 64 weights per thread as 32 f32x2 regs (shared by both chains)
    ull wp[32];
    const ull* Wp = (const ull*)W_hh;
#pragma unroll
    for (int j = 0; j < 32; j++) wp[j] = Wp[grow * 128 + kc * 32 + j];
    for (int i = tid; i < 272; i += 384) {
        h_buf[0][0][i] = 0.f;
        h_buf[1][0][i] = 0.f;
    }

    const size_t gxA = (size_t)(bA * 8 + s) * 4096 * 96;
    const size_t gxB = (size_t)(bB * 8 + s) * 4096 * 96;
    float bhr = 0.f, bhz = 0.f, bhn = 0.f;
    float gArr = 0.f, gAz = 0.f, gAn = 0.f, gBr = 0.f, gBz = 0.f, gBn = 0.f;
    float holdA = 0.f, holdB = 0.f;
    ull *pubA = nullptr, *pubB = nullptr;
    const ull *pollA = nullptr, *pollB = nullptr;
    int sidx = 0;
    if (warp == 0) {
        int ch = (s << 5) + lane;
        bhr = b_hh[ch]; bhz = b_hh[256 + ch]; bhn = b_hh[512 + ch];
        gArr = g_gx[gxA + lane];
        gAz = g_gx[gxA + 32 + lane];
        gAn = g_gx[gxA + 64 + lane];
        gBr = g_gx[gxB + lane];
        gBz = g_gx[gxB + 32 + lane];
        gBn = g_gx[gxB + 64 + lane];
        pubA = &g_hv[(size_t)bA * 256 + ch];   // + bin*4096
        pubB = &g_hv[(size_t)bB * 256 + ch];
    } else if (warp <= 8) {
        int c = ((warp - 1) << 5) + lane;
        pollA = &g_hv[(size_t)bA * 256 + c];
        pollB = &g_hv[(size_t)bB * 256 + c];
        sidx = (c >> 6) * 68 + (c & 63);
    }
    __syncthreads();

    for (int t = 0; t < 4096; t++) {
        const int par = t & 1;
        const int bin = par ^ 1;
        const bool last = (t == 4095);

        // ---------------- phase 1: gemv chain A on h_A[t] ----------------
        {
            ull accA = 0ULL, accB = 0ULL;
            const ulonglong2* hb = (const ulonglong2*)&h_buf[0][par][kc * 68];
#pragma unroll
            for (int j = 0; j < 16; j++) {
                ulonglong2 hv = hb[j];
                fma2(accA, wp[2 * j + 0], hv.x);
                fma2(accB, wp[2 * j + 1], hv.y);
            }
            float ax, ay, bx, by;
            unpack2(accA, ax, ay); unpack2(accB, bx, by);
            float r0 = (ax + ay) + (bx + by);
            r0 += __shfl_xor_sync(0xffffffffu, r0, 1);
            r0 += __shfl_xor_sync(0xffffffffu, r0, 2);
            if (kc == 0) gates_s[0][p] = r0;
        }
        __syncthreads();

        // ---- phase 3: act_A + publish_A(t+1)  ||  gather_B(t) ----
        if (warp == 0) {
            float r = fast_sig(gArr + gates_s[0][lane] + bhr);
            float z = fast_sig(gAz + gates_s[0][32 + lane] + bhz);
            float n = fast_tanh(gAn + fmaf(r, gates_s[0][64 + lane] + bhn, 0.f));
            float hnew = fmaf(z, holdA - n, n);
            holdA = hnew;
            if (!last) {
                ull w = ((ull)(uint32_t)(t + 1) << 32) |
                        (ull)__float_as_uint(hnew);
                st_relaxed_gpu_b64(pubA + bin * 4096, w);
            }
            out[((size_t)bA * 4096 + t) * 256 + (s << 5) + lane] = hnew;
            int tn = last ? t : (t + 1);
            gArr = __ldg(&g_gx[gxA + (size_t)tn * 96 + lane]);
            gAz = __ldg(&g_gx[gxA + (size_t)tn * 96 + 32 + lane]);
            gAn = __ldg(&g_gx[gxA + (size_t)tn * 96 + 64 + lane]);
        } else if (warp <= 8 && t > 0) {
            // gather h_B[t] from word set 'par' (published iter t-1 phase 7)
            const ull* wptr = pollB + par * 4096;
            const uint32_t target = (uint32_t)t;
            ull w;
            for (;;) {
                ull w0 = ld_relaxed_gpu_b64(wptr);
                ull w1 = ld_relaxed_gpu_b64(wptr);
                if ((uint32_t)(w0 >> 32) == target) { w = w0; break; }
                if ((uint32_t)(w1 >> 32) == target) { w = w1; break; }
            }
            h_buf[1][par][sidx] = __uint_as_float((uint32_t)w);
        }
        __syncthreads();

        // ---------------- phase 5: gemv chain B on h_B[t] ----------------
        {
            ull accA = 0ULL, accB = 0ULL;
            const ulonglong2* hb = (const ulonglong2*)&h_buf[1][par][kc * 68];
#pragma unroll
            for (int j = 0; j < 16; j++) {
                ulonglong2 hv = hb[j];
                fma2(accA, wp[2 * j + 0], hv.x);
                fma2(accB, wp[2 * j + 1], hv.y);
            }
            float ax, ay, bx, by;
            unpack2(accA, ax, ay); unpack2(accB, bx, by);
            float r0 = (ax + ay) + (bx + by);
            r0 += __shfl_xor_sync(0xffffffffu, r0, 1);
            r0 += __shfl_xor_sync(0xffffffffu, r0, 2);
            if (kc == 0) gates_s[1][p] = r0;
        }
        __syncthreads();

        // ---- phase 7: act_B + publish_B(t+1)  ||  gather_A(t+1) ----
        if (warp == 0) {
            float r = fast_sig(gBr + gates_s[1][lane] + bhr);
            float z = fast_sig(gBz + gates_s[1][32 + lane] + bhz);
            float n = fast_tanh(gBn + fmaf(r, gates_s[1][64 + lane] + bhn, 0.f));
            float hnew = fmaf(z, holdB - n, n);
            holdB = hnew;
            if (!last) {
                ull w = ((ull)(uint32_t)(t + 1) << 32) |
                        (ull)__float_as_uint(hnew);
                st_relaxed_gpu_b64(pubB + bin * 4096, w);
            }
            out[((size_t)bB * 4096 + t) * 256 + (s << 5) + lane] = hnew;
            int tn = last ? t : (t + 1);
            gBr = __ldg(&g_gx[gxB + (size_t)tn * 96 + lane]);
            gBz = __ldg(&g_gx[gxB + (size_t)tn * 96 + 32 + lane]);
            gBn = __ldg(&g_gx[gxB + (size_t)tn * 96 + 64 + lane]);
        } else if (warp <= 8 && !last) {
            // gather h_A[t+1] from word set 'bin' (published this iter ph.3)
            const ull* wptr = pollA + bin * 4096;
            const uint32_t target = (uint32_t)(t + 1);
            ull w;
            for (;;) {
                ull w0 = ld_relaxed_gpu_b64(wptr);
                ull w1 = ld_relaxed_gpu_b64(wptr);
                if ((uint32_t)(w0 >> 32) == target) { w = w0; break; }
                if ((uint32_t)(w1 >> 32) == target) { w = w1; break; }
            }
            h_buf[0][bin][sidx] = __uint_as_float((uint32_t)w);
        }
        __syncthreads();
    }
}

// ============================================================================
extern "C" void kernel_launch(void* const* d_in, const int* in_sizes, int n_in,
                              void* d_out, int out_size)
{
    const float* features = (const float*)d_in[0];
    const float* W1   = (const float*)d_in[1];
    const float* b1   = (const float*)d_in[2];
    const float* W2   = (const float*)d_in[3];
    const float* b2   = (const float*)d_in[4];
    const float* Wt   = (const float*)d_in[5];
    const float* bt   = (const float*)d_in[6];
    const float* W_ih = (const float*)d_in[7];
    const float* W_hh = (const float*)d_in[8];
    const float* b_ih = (const float*)d_in[9];
    const float* b_hh = (const float*)d_in[10];
    float* out = (float*)d_out;

    conv1_kernel<<<dim3(128, 16), 256>>>(features, W1, b1);
    prep_kernel<<<768, 768>>>(W2, W_ih);
    gemm_kernel<0><<<dim3(128, 2), 256>>>(nullptr, b2);
    gemm_kernel<1><<<dim3(128, 8), 256>>>(Wt, bt);
    gemm_kernel<2><<<dim3(512, 6), 256>>>(nullptr, b_ih);
    gru_kernel<<<64, 384>>>(W_hh, b_hh, out);
}